// round 4
// baseline (speedup 1.0000x reference)
#include <cuda_runtime.h>
#include <cstdint>

// Problem constants
#define BB 64
#define TT 2048
#define HH 256
#define G4 1024
#define MTOT (BB * TT)

typedef unsigned long long ull;

// ---------- f32x2 helpers ----------
__device__ __forceinline__ ull fma2(ull a, ull b, ull c) {
    ull d; asm("fma.rn.f32x2 %0,%1,%2,%3;" : "=l"(d) : "l"(a), "l"(b), "l"(c)); return d;
}
__device__ __forceinline__ ull pack2(float x, float y) {
    ull d; asm("mov.b64 %0,{%1,%2};" : "=l"(d) : "f"(x), "f"(y)); return d;
}
__device__ __forceinline__ float2 unpk2(ull a) {
    float2 r; asm("mov.b64 {%0,%1},%2;" : "=f"(r.x), "=f"(r.y) : "l"(a)); return r;
}

__device__ __forceinline__ uint32_t s2u(const void* p) {
    return (uint32_t)__cvta_generic_to_shared(p);
}
__device__ __forceinline__ uint32_t mapa_u32(uint32_t saddr, uint32_t rank) {
    uint32_t ra;
    asm("mapa.shared::cluster.u32 %0, %1, %2;" : "=r"(ra) : "r"(saddr), "r"(rank));
    return ra;
}
__device__ __forceinline__ void sts_cluster_b64(uint32_t ra, ull v) {
    asm volatile("st.shared::cluster.b64 [%0], %1;" :: "r"(ra), "l"(v) : "memory");
}
__device__ __forceinline__ void mbar_init(uint32_t a, uint32_t cnt) {
    asm volatile("mbarrier.init.shared.b64 [%0], %1;" :: "r"(a), "r"(cnt) : "memory");
}
__device__ __forceinline__ void mbar_arrive_remote(uint32_t ra) {
    asm volatile("mbarrier.arrive.release.cluster.shared::cluster.b64 _, [%0];"
                 :: "r"(ra) : "memory");
}
__device__ __forceinline__ void mbar_wait(uint32_t a, uint32_t ph) {
    asm volatile(
        "{\n\t.reg .pred P;\n"
        "W%=:\n\tmbarrier.try_wait.parity.acquire.cluster.shared::cta.b64 P, [%0], %1;\n"
        "\t@!P bra W%=;\n\t}"
        :: "r"(a), "r"(ph) : "memory");
}
__device__ __forceinline__ void fence_cluster() {
    asm volatile("fence.acq_rel.cluster;" ::: "memory");
}
__device__ __forceinline__ void named_bar(int id, int n) {
    asm volatile("bar.sync %0, %1;" :: "r"(id), "r"(n) : "memory");
}
__device__ __forceinline__ void cluster_sync_() {
    asm volatile("barrier.cluster.arrive.aligned;\n\tbarrier.cluster.wait.aligned;" ::: "memory");
}
__device__ __forceinline__ uint32_t ctarank() {
    uint32_t r; asm("mov.u32 %0, %%cluster_ctarank;" : "=r"(r)); return r;
}

__device__ __forceinline__ float fsig(float x)  { return 1.0f / (1.0f + __expf(-x)); }
__device__ __forceinline__ float ftanh(float x) { return 2.0f / (1.0f + __expf(-2.0f * x)) - 1.0f; }

// ---------- scratch ----------
__device__ float g_xg[(size_t)MTOT * G4];
__device__ float g_y0[(size_t)MTOT * HH];
__device__ float g_y1[(size_t)MTOT * HH];

// ============================================================================
// Phase A: GEMM (unchanged)
// ============================================================================
__global__ void __launch_bounds__(256) gemm_kernel(
    const float* __restrict__ Ain, int useAin,
    const float* __restrict__ W,
    const float* __restrict__ b1, const float* __restrict__ b2)
{
    const float* A = useAin ? Ain : g_y0;
    float* C = g_xg;

    __shared__ float As[16][132];
    __shared__ float Bs[16][68];

    const int tid = threadIdx.x;
    const int bm = blockIdx.y * 128;
    const int bn = blockIdx.x * 64;
    const int tx = tid & 15;
    const int ty = tid >> 4;

    ull acc[8][2];
#pragma unroll
    for (int i = 0; i < 8; i++) { acc[i][0] = 0ull; acc[i][1] = 0ull; }

    for (int kt = 0; kt < HH; kt += 16) {
#pragma unroll
        for (int i = 0; i < 2; i++) {
            int idx = tid + i * 256;
            int r = idx >> 2, q = idx & 3;
            float4 v = *(const float4*)(A + (size_t)(bm + r) * HH + kt + q * 4);
            As[q * 4 + 0][r] = v.x; As[q * 4 + 1][r] = v.y;
            As[q * 4 + 2][r] = v.z; As[q * 4 + 3][r] = v.w;
        }
        {
            int r = tid >> 2, q = tid & 3;
            float4 v = *(const float4*)(W + (size_t)(bn + r) * HH + kt + q * 4);
            Bs[q * 4 + 0][r] = v.x; Bs[q * 4 + 1][r] = v.y;
            Bs[q * 4 + 2][r] = v.z; Bs[q * 4 + 3][r] = v.w;
        }
        __syncthreads();
#pragma unroll
        for (int k = 0; k < 16; k++) {
            float4 b4 = *(const float4*)&Bs[k][tx * 4];
            ull b01 = pack2(b4.x, b4.y);
            ull b23 = pack2(b4.z, b4.w);
            float4 a0 = *(const float4*)&As[k][ty * 8];
            float4 a1 = *(const float4*)&As[k][ty * 8 + 4];
            float am[8] = {a0.x, a0.y, a0.z, a0.w, a1.x, a1.y, a1.z, a1.w};
#pragma unroll
            for (int mi = 0; mi < 8; mi++) {
                ull ad = pack2(am[mi], am[mi]);
                acc[mi][0] = fma2(ad, b01, acc[mi][0]);
                acc[mi][1] = fma2(ad, b23, acc[mi][1]);
            }
        }
        __syncthreads();
    }

    float4 bias;
    bias.x = b1[bn + tx * 4 + 0] + b2[bn + tx * 4 + 0];
    bias.y = b1[bn + tx * 4 + 1] + b2[bn + tx * 4 + 1];
    bias.z = b1[bn + tx * 4 + 2] + b2[bn + tx * 4 + 2];
    bias.w = b1[bn + tx * 4 + 3] + b2[bn + tx * 4 + 3];
#pragma unroll
    for (int mi = 0; mi < 8; mi++) {
        float2 u = unpk2(acc[mi][0]);
        float2 v = unpk2(acc[mi][1]);
        float4 o = {u.x + bias.x, u.y + bias.y, v.x + bias.z, v.y + bias.w};
        *(float4*)(C + (size_t)(bm + ty * 8 + mi) * G4 + bn + tx * 4) = o;
    }
}

// ============================================================================
// Phase B v3: 16 clusters x 8 CTAs, 256 threads/CTA (reg cap 255 -> no spill).
// 8 warps = 4 k-slices (64 k) x 2 row-halves; thread owns row pair, wp[64].
// Sync = slice-level mbarriers (no cluster.sync in the loop):
//   full[r][buf] (count 1): rank r published its h slice for buf.
//   empty[buf]  (count 16): all 16 reader-warps cluster-wide released buf.
// ============================================================================
struct RS {
    ull   hd[2][256][4];       // (h,h) duplicated, [buf][k][b]   16KB
    float red[2][4][4][128];   // [buf][kslice][b][row]           16KB
    ull   full[8][2];
    ull   empty[2];
};

extern __shared__ __align__(16) char smem_raw[];

__global__ void __launch_bounds__(256, 1) __cluster_dims__(8, 1, 1)
rnn_kernel(const float* __restrict__ whh, int layer)
{
    RS* sm = (RS*)smem_raw;
    float* yout = layer ? g_y1 : g_y0;

    const int tid  = threadIdx.x;
    const int lane = tid & 31;
    const int wid  = tid >> 5;
    const int ks   = wid & 3;      // k-slice 0..3 (64 k each)
    const int rh   = wid >> 2;     // row half
    const int s    = (int)ctarank();
    const int cl   = blockIdx.x >> 3;
    const int b0   = cl * 4;

    const int pr = rh * 32 + lane;       // row pair 0..63
    const int r0 = 2 * pr;
    const int grow0 = ((r0 >> 5) << 8) + s * 32 + (r0 & 31);
    const int kb = ks * 64;

    // ---- weights in registers: wp[k] = (w[r0][kb+k], w[r0+1][kb+k]) ----
    ull wp[64];
    {
        const float* w0p = whh + (size_t)grow0 * HH + kb;
        const float* w1p = w0p + HH;
#pragma unroll
        for (int q = 0; q < 16; q++) {
            float4 v0 = *(const float4*)(w0p + 4 * q);
            float4 v1 = *(const float4*)(w1p + 4 * q);
            wp[4 * q + 0] = pack2(v0.x, v1.x);
            wp[4 * q + 1] = pack2(v0.y, v1.y);
            wp[4 * q + 2] = pack2(v0.z, v1.z);
            wp[4 * q + 3] = pack2(v0.w, v1.w);
        }
    }

    // ---- init barriers + zero h ----
    if (tid == 0) {
#pragma unroll
        for (int r = 0; r < 8; r++) { mbar_init(s2u(&sm->full[r][0]), 1); mbar_init(s2u(&sm->full[r][1]), 1); }
        mbar_init(s2u(&sm->empty[0]), 16);
        mbar_init(s2u(&sm->empty[1]), 16);
    }
    for (int i = tid; i < 2 * 256 * 4; i += 256) ((ull*)sm->hd)[i] = 0ull;
    __syncthreads();
    cluster_sync_();   // barriers visible cluster-wide before any remote op

    // remote empty addresses (lane 0 -> rank 2ks, lane 1 -> rank 2ks+1)
    uint32_t eA0 = 0, eA1 = 0;
    if (lane < 2) {
        uint32_t rr = 2 * ks + lane;
        eA0 = mapa_u32(s2u(&sm->empty[0]), rr);
        eA1 = mapa_u32(s2u(&sm->empty[1]), rr);
    }

    // cell identity (tid < 128): tid = cb*32 + cd
    const int cb = tid >> 5;
    const int cd = tid & 31;
    const float* xgb = g_xg + (size_t)(b0 + cb) * TT * G4 + s * 32 + cd;
    float* youtp = yout + (size_t)(b0 + cb) * TT * HH + s * 32 + cd;
    const uint32_t la0 = s2u(&sm->hd[0][s * 32 + cd][cb]);
    const uint32_t la1 = s2u(&sm->hd[1][s * 32 + cd][cb]);
    const uint32_t fullA0 = s2u(&sm->full[s][0]);
    const uint32_t fullA1 = s2u(&sm->full[s][1]);

    const uint32_t fw0 = s2u(&sm->full[2 * ks][0]);
    const uint32_t fw1 = s2u(&sm->full[2 * ks + 1][0]);

    float creg = 0.0f;

    for (int t = 0; t < TT; t++) {
        const int p = t & 1;

        // prefetch xg (consumed after k-loop)
        float xv0 = 0.f, xv1 = 0.f, xv2 = 0.f, xv3 = 0.f;
        if (tid < 128) {
            const float* xp = xgb + (size_t)t * G4;
            xv0 = __ldg(xp);        xv1 = __ldg(xp + 256);
            xv2 = __ldg(xp + 512);  xv3 = __ldg(xp + 768);
        }

        // wait for the two source CTAs of this k-slice to publish h(buf p)
        if (t > 0) {
            const uint32_t fph = (uint32_t)(((t >> 1) - 1 + (t & 1)) & 1);
            mbar_wait(fw0 + (uint32_t)p * 8u, fph);
            mbar_wait(fw1 + (uint32_t)p * 8u, fph);
        }

        // ---- k-loop: 64 iters, 2x LDS.128 broadcast + 4x FFMA2 ----
        ull a0 = 0ull, a1 = 0ull, a2 = 0ull, a3 = 0ull;
        const ulonglong2* hb = (const ulonglong2*)&sm->hd[p][kb][0];
#pragma unroll
        for (int kk = 0; kk < 64; kk++) {
            ulonglong2 h01 = hb[2 * kk];
            ulonglong2 h23 = hb[2 * kk + 1];
            ull w = wp[kk];
            a0 = fma2(w, h01.x, a0);
            a1 = fma2(w, h01.y, a1);
            a2 = fma2(w, h23.x, a2);
            a3 = fma2(w, h23.y, a3);
        }
        *(ull*)&sm->red[p][ks][0][r0] = a0;
        *(ull*)&sm->red[p][ks][1][r0] = a1;
        *(ull*)&sm->red[p][ks][2][r0] = a2;
        *(ull*)&sm->red[p][ks][3][r0] = a3;

        // this warp is done reading hd[p] -> release buf p to its source CTAs
        __syncwarp();
        if (lane < 2) mbar_arrive_remote(p ? eA1 : eA0);

        __syncthreads();   // partials visible to cell threads

        // ---- merged reduce + activation + cell (threads 0..127) ----
        if (tid < 128) {
            float si = xv0, sf = xv1, sg = xv2, so = xv3;
#pragma unroll
            for (int s4 = 0; s4 < 4; s4++) {
                si += sm->red[p][s4][cb][cd];
                sf += sm->red[p][s4][cb][32 + cd];
                sg += sm->red[p][s4][cb][64 + cd];
                so += sm->red[p][s4][cb][96 + cd];
            }
            float iv = fsig(si), fv = fsig(sf), gv = ftanh(sg), ov = fsig(so);
            creg = fv * creg + iv * gv;
            float hv = ov * ftanh(creg);
            youtp[(size_t)t * HH] = hv;

            // make sure everyone released buf p^1 before overwriting it
            if (t >= 1) mbar_wait(s2u(&sm->empty[p ^ 1]), (uint32_t)(((t - 1) >> 1) & 1));

            ull hvd = pack2(hv, hv);
            const uint32_t la = p ? la0 : la1;   // writing buf p^1
#pragma unroll
            for (int rr = 0; rr < 8; rr++) sts_cluster_b64(mapa_u32(la, (uint32_t)rr), hvd);

            fence_cluster();
            named_bar(1, 128);
            if (tid == 0) {
                const uint32_t fa = p ? fullA0 : fullA1;
#pragma unroll
                for (int rr = 0; rr < 8; rr++) mbar_arrive_remote(mapa_u32(fa, (uint32_t)rr));
            }
        }
    }
    cluster_sync_();   // no CTA may exit while peers still target its SMEM
}

// ============================================================================
// Head
// ============================================================================
__global__ void head_kernel(const float* __restrict__ wlin,
                            const float* __restrict__ blin,
                            float* __restrict__ out)
{
    int b = blockIdx.x, lane = threadIdx.x;
    const float* hp = g_y1 + ((size_t)b * TT + (TT - 1)) * HH;
    float ssum = 0.0f;
    for (int k = lane; k < HH; k += 32) ssum += hp[k] * wlin[k];
#pragma unroll
    for (int o = 16; o; o >>= 1) ssum += __shfl_down_sync(0xffffffffu, ssum, o);
    if (lane == 0) out[b] = ssum + blin[0];
}

// ============================================================================
extern "C" void kernel_launch(void* const* d_in, const int* in_sizes, int n_in,
                              void* d_out, int out_size)
{
    const float* input = (const float*)d_in[0];
    const float* w_ih  = (const float*)d_in[1];
    const float* w_hh  = (const float*)d_in[2];
    const float* b_ih  = (const float*)d_in[3];
    const float* b_hh  = (const float*)d_in[4];
    const float* w_lin = (const float*)d_in[5];
    const float* b_lin = (const float*)d_in[6];
    float* out = (float*)d_out;

    cudaFuncSetAttribute(rnn_kernel, cudaFuncAttributeMaxDynamicSharedMemorySize,
                         (int)sizeof(RS));

    dim3 gg(G4 / 64, MTOT / 128);

    gemm_kernel<<<gg, 256>>>(input, 1, w_ih, b_ih, b_hh);
    rnn_kernel<<<128, 256, sizeof(RS)>>>(w_hh, 0);
    gemm_kernel<<<gg, 256>>>(input, 0, w_ih + (size_t)G4 * HH, b_ih + G4, b_hh + G4);
    rnn_kernel<<<128, 256, sizeof(RS)>>>(w_hh + (size_t)G4 * HH, 1);
    head_kernel<<<BB, 32>>>(w_lin, b_lin, out);
}

// round 8
// speedup vs baseline: 1.7095x; 1.7095x over previous
#include <cuda_runtime.h>
#include <cstdint>

// Problem constants
#define BB 64
#define TT 2048
#define HH 256
#define G4 1024
#define MTOT (BB * TT)

typedef unsigned long long ull;

// ---------- f32x2 helpers ----------
__device__ __forceinline__ ull fma2(ull a, ull b, ull c) {
    ull d; asm("fma.rn.f32x2 %0,%1,%2,%3;" : "=l"(d) : "l"(a), "l"(b), "l"(c)); return d;
}
__device__ __forceinline__ ull pack2(float x, float y) {
    ull d; asm("mov.b64 %0,{%1,%2};" : "=l"(d) : "f"(x), "f"(y)); return d;
}
__device__ __forceinline__ float2 unpk2(ull a) {
    float2 r; asm("mov.b64 {%0,%1},%2;" : "=f"(r.x), "=f"(r.y) : "l"(a)); return r;
}

__device__ __forceinline__ uint32_t s2u(const void* p) {
    return (uint32_t)__cvta_generic_to_shared(p);
}
__device__ __forceinline__ uint32_t mapa_u32(uint32_t saddr, uint32_t rank) {
    uint32_t ra;
    asm("mapa.shared::cluster.u32 %0, %1, %2;" : "=r"(ra) : "r"(saddr), "r"(rank));
    return ra;
}
__device__ __forceinline__ void sts_cluster_b64(uint32_t ra, ull v) {
    asm volatile("st.shared::cluster.b64 [%0], %1;" :: "r"(ra), "l"(v) : "memory");
}
__device__ __forceinline__ void cluster_sync_() {
    asm volatile("barrier.cluster.arrive.aligned;\n\tbarrier.cluster.wait.aligned;" ::: "memory");
}
__device__ __forceinline__ uint32_t ctarank() {
    uint32_t r; asm("mov.u32 %0, %%cluster_ctarank;" : "=r"(r)); return r;
}

__device__ __forceinline__ float fsig(float x)  { return 1.0f / (1.0f + __expf(-x)); }
__device__ __forceinline__ float ftanh(float x) { return 2.0f / (1.0f + __expf(-2.0f * x)) - 1.0f; }

// ---------- scratch ----------
__device__ float g_xg[(size_t)MTOT * G4];
__device__ float g_y0[(size_t)MTOT * HH];
__device__ float g_y1[(size_t)MTOT * HH];

// ============================================================================
// Phase A: GEMM (unchanged)
// ============================================================================
__global__ void __launch_bounds__(256) gemm_kernel(
    const float* __restrict__ Ain, int useAin,
    const float* __restrict__ W,
    const float* __restrict__ b1, const float* __restrict__ b2)
{
    const float* A = useAin ? Ain : g_y0;
    float* C = g_xg;

    __shared__ float As[16][132];
    __shared__ float Bs[16][68];

    const int tid = threadIdx.x;
    const int bm = blockIdx.y * 128;
    const int bn = blockIdx.x * 64;
    const int tx = tid & 15;
    const int ty = tid >> 4;

    ull acc[8][2];
#pragma unroll
    for (int i = 0; i < 8; i++) { acc[i][0] = 0ull; acc[i][1] = 0ull; }

    for (int kt = 0; kt < HH; kt += 16) {
#pragma unroll
        for (int i = 0; i < 2; i++) {
            int idx = tid + i * 256;
            int r = idx >> 2, q = idx & 3;
            float4 v = *(const float4*)(A + (size_t)(bm + r) * HH + kt + q * 4);
            As[q * 4 + 0][r] = v.x; As[q * 4 + 1][r] = v.y;
            As[q * 4 + 2][r] = v.z; As[q * 4 + 3][r] = v.w;
        }
        {
            int r = tid >> 2, q = tid & 3;
            float4 v = *(const float4*)(W + (size_t)(bn + r) * HH + kt + q * 4);
            Bs[q * 4 + 0][r] = v.x; Bs[q * 4 + 1][r] = v.y;
            Bs[q * 4 + 2][r] = v.z; Bs[q * 4 + 3][r] = v.w;
        }
        __syncthreads();
#pragma unroll
        for (int k = 0; k < 16; k++) {
            float4 b4 = *(const float4*)&Bs[k][tx * 4];
            ull b01 = pack2(b4.x, b4.y);
            ull b23 = pack2(b4.z, b4.w);
            float4 a0 = *(const float4*)&As[k][ty * 8];
            float4 a1 = *(const float4*)&As[k][ty * 8 + 4];
            float am[8] = {a0.x, a0.y, a0.z, a0.w, a1.x, a1.y, a1.z, a1.w};
#pragma unroll
            for (int mi = 0; mi < 8; mi++) {
                ull ad = pack2(am[mi], am[mi]);
                acc[mi][0] = fma2(ad, b01, acc[mi][0]);
                acc[mi][1] = fma2(ad, b23, acc[mi][1]);
            }
        }
        __syncthreads();
    }

    float4 bias;
    bias.x = b1[bn + tx * 4 + 0] + b2[bn + tx * 4 + 0];
    bias.y = b1[bn + tx * 4 + 1] + b2[bn + tx * 4 + 1];
    bias.z = b1[bn + tx * 4 + 2] + b2[bn + tx * 4 + 2];
    bias.w = b1[bn + tx * 4 + 3] + b2[bn + tx * 4 + 3];
#pragma unroll
    for (int mi = 0; mi < 8; mi++) {
        float2 u = unpk2(acc[mi][0]);
        float2 v = unpk2(acc[mi][1]);
        float4 o = {u.x + bias.x, u.y + bias.y, v.x + bias.z, v.y + bias.w};
        *(float4*)(C + (size_t)(bm + ty * 8 + mi) * G4 + bn + tx * 4) = o;
    }
}

// ============================================================================
// Phase B v4: 8 clusters x 8 CTAs x 256 threads. Each cluster handles TWO
// independent batch groups (8 batches) per step; weights (in registers,
// wp[64] = 128 regs) are shared by both groups. One __syncthreads + one
// cluster.sync per step covers both groups. Epilogue: 128 threads per group
// in parallel. Sync = plain cluster.sync (R4's mbarrier scheme reverted).
// ============================================================================
#define HD_GRP_BYTES (256 * 4 * 8)          // one [k][b] ull plane
#define HD_BUF_BYTES (2 * HD_GRP_BYTES)     // both groups of one buffer

struct RS {
    ull   hd[2][2][256][4];     // [buf][group][k][b], (h,h) duplicated  32KB
    float red[2][4][4][128];    // [group][kslice][b][row]               16KB
};

extern __shared__ __align__(16) char smem_raw[];

__global__ void __launch_bounds__(256, 1) __cluster_dims__(8, 1, 1)
rnn_kernel(const float* __restrict__ whh, int layer)
{
    RS* sm = (RS*)smem_raw;
    float* yout = layer ? g_y1 : g_y0;

    const int tid  = threadIdx.x;
    const int lane = tid & 31;
    const int wid  = tid >> 5;
    const int ks   = wid & 3;      // k-slice 0..3 (64 k each)
    const int rh   = wid >> 2;     // row half
    const int s    = (int)ctarank();
    const int cl   = blockIdx.x >> 3;
    const int b0   = cl * 8;       // 8 batches per cluster

    const int pr = rh * 32 + lane;       // row pair 0..63
    const int r0 = 2 * pr;
    const int grow0 = ((r0 >> 5) << 8) + s * 32 + (r0 & 31);
    const int kb = ks * 64;

    // ---- weights in registers: wp[k] = (w[r0][kb+k], w[r0+1][kb+k]) ----
    ull wp[64];
    {
        const float* w0p = whh + (size_t)grow0 * HH + kb;
        const float* w1p = w0p + HH;
#pragma unroll
        for (int q = 0; q < 16; q++) {
            float4 v0 = *(const float4*)(w0p + 4 * q);
            float4 v1 = *(const float4*)(w1p + 4 * q);
            wp[4 * q + 0] = pack2(v0.x, v1.x);
            wp[4 * q + 1] = pack2(v0.y, v1.y);
            wp[4 * q + 2] = pack2(v0.z, v1.z);
            wp[4 * q + 3] = pack2(v0.w, v1.w);
        }
    }

    // zero all h buffers (2 bufs x 2 groups)
    for (int i = tid; i < 2 * 2 * 256 * 4; i += 256) ((ull*)sm->hd)[i] = 0ull;
    __syncthreads();
    cluster_sync_();

    // ---- cell identity: every thread owns one cell ----
    // gsel = group (0/1), cb = batch-in-group, cd = dim-in-slice
    const int gsel = tid >> 7;
    const int cb   = (tid >> 5) & 3;
    const int cd   = tid & 31;
    const int gb   = b0 + gsel * 4 + cb;                 // global batch
    const float* xgb = g_xg + (size_t)gb * TT * G4 + s * 32 + cd;
    float* youtp = yout + (size_t)gb * TT * HH + s * 32 + cd;
    // local smem address of this cell's h slot in buf0; remote = mapa + buf offset
    const uint32_t la_buf0 = s2u(&sm->hd[0][gsel][s * 32 + cd][cb]);

    float creg = 0.0f;

    for (int t = 0; t < TT; t++) {
        const int p = t & 1;

        // prefetch xg for this thread's cell (consumed after the k-loops)
        float xv0, xv1, xv2, xv3;
        {
            const float* xp = xgb + (size_t)t * G4;
            xv0 = __ldg(xp);        xv1 = __ldg(xp + 256);
            xv2 = __ldg(xp + 512);  xv3 = __ldg(xp + 768);
        }

        // ---- k-loop, group A ----
        {
            ull a0 = 0ull, a1 = 0ull, a2 = 0ull, a3 = 0ull;
            const ulonglong2* hb = (const ulonglong2*)&sm->hd[p][0][kb][0];
#pragma unroll
            for (int kk = 0; kk < 64; kk++) {
                ulonglong2 h01 = hb[2 * kk];
                ulonglong2 h23 = hb[2 * kk + 1];
                ull w = wp[kk];
                a0 = fma2(w, h01.x, a0);
                a1 = fma2(w, h01.y, a1);
                a2 = fma2(w, h23.x, a2);
                a3 = fma2(w, h23.y, a3);
            }
            *(ull*)&sm->red[0][ks][0][r0] = a0;
            *(ull*)&sm->red[0][ks][1][r0] = a1;
            *(ull*)&sm->red[0][ks][2][r0] = a2;
            *(ull*)&sm->red[0][ks][3][r0] = a3;
        }
        // ---- k-loop, group B (same weights, independent h) ----
        {
            ull a0 = 0ull, a1 = 0ull, a2 = 0ull, a3 = 0ull;
            const ulonglong2* hb = (const ulonglong2*)&sm->hd[p][1][kb][0];
#pragma unroll
            for (int kk = 0; kk < 64; kk++) {
                ulonglong2 h01 = hb[2 * kk];
                ulonglong2 h23 = hb[2 * kk + 1];
                ull w = wp[kk];
                a0 = fma2(w, h01.x, a0);
                a1 = fma2(w, h01.y, a1);
                a2 = fma2(w, h23.x, a2);
                a3 = fma2(w, h23.y, a3);
            }
            *(ull*)&sm->red[1][ks][0][r0] = a0;
            *(ull*)&sm->red[1][ks][1][r0] = a1;
            *(ull*)&sm->red[1][ks][2][r0] = a2;
            *(ull*)&sm->red[1][ks][3][r0] = a3;
        }
        __syncthreads();

        // ---- merged reduce + activation + cell, ALL 256 threads ----
        {
            float si = xv0, sf = xv1, sg = xv2, so = xv3;
#pragma unroll
            for (int s4 = 0; s4 < 4; s4++) {
                si += sm->red[gsel][s4][cb][cd];
                sf += sm->red[gsel][s4][cb][32 + cd];
                sg += sm->red[gsel][s4][cb][64 + cd];
                so += sm->red[gsel][s4][cb][96 + cd];
            }
            float iv = fsig(si), fv = fsig(sf), gv = ftanh(sg), ov = fsig(so);
            creg = fv * creg + iv * gv;
            float hv = ov * ftanh(creg);
            youtp[(size_t)t * HH] = hv;

            // publish duplicated h to all 8 CTAs' buffer p^1
            ull hvd = pack2(hv, hv);
            const uint32_t la = la_buf0 + (uint32_t)((p ^ 1) * HD_BUF_BYTES);
#pragma unroll
            for (int rr = 0; rr < 8; rr++)
                sts_cluster_b64(mapa_u32(la, (uint32_t)rr), hvd);
        }
        cluster_sync_();
    }
}

// ============================================================================
// Head
// ============================================================================
__global__ void head_kernel(const float* __restrict__ wlin,
                            const float* __restrict__ blin,
                            float* __restrict__ out)
{
    int b = blockIdx.x, lane = threadIdx.x;
    const float* hp = g_y1 + ((size_t)b * TT + (TT - 1)) * HH;
    float ssum = 0.0f;
    for (int k = lane; k < HH; k += 32) ssum += hp[k] * wlin[k];
#pragma unroll
    for (int o = 16; o; o >>= 1) ssum += __shfl_down_sync(0xffffffffu, ssum, o);
    if (lane == 0) out[b] = ssum + blin[0];
}

// ============================================================================
extern "C" void kernel_launch(void* const* d_in, const int* in_sizes, int n_in,
                              void* d_out, int out_size)
{
    const float* input = (const float*)d_in[0];
    const float* w_ih  = (const float*)d_in[1];
    const float* w_hh  = (const float*)d_in[2];
    const float* b_ih  = (const float*)d_in[3];
    const float* b_hh  = (const float*)d_in[4];
    const float* w_lin = (const float*)d_in[5];
    const float* b_lin = (const float*)d_in[6];
    float* out = (float*)d_out;

    cudaFuncSetAttribute(rnn_kernel, cudaFuncAttributeMaxDynamicSharedMemorySize,
                         (int)sizeof(RS));

    dim3 gg(G4 / 64, MTOT / 128);

    gemm_kernel<<<gg, 256>>>(input, 1, w_ih, b_ih, b_hh);
    rnn_kernel<<<64, 256, sizeof(RS)>>>(w_hh, 0);
    gemm_kernel<<<gg, 256>>>(input, 0, w_ih + (size_t)G4 * HH, b_ih + G4, b_hh + G4);
    rnn_kernel<<<64, 256, sizeof(RS)>>>(w_hh + (size_t)G4 * HH, 1);
    head_kernel<<<BB, 32>>>(w_lin, b_lin, out);
}

// round 10
// speedup vs baseline: 1.8419x; 1.0775x over previous
#include <cuda_runtime.h>
#include <cstdint>

// Problem constants
#define BB 64
#define TT 2048
#define HH 256
#define G4 1024
#define MTOT (BB * TT)

typedef unsigned long long ull;

// ---------- f32x2 helpers ----------
__device__ __forceinline__ ull fma2(ull a, ull b, ull c) {
    ull d; asm("fma.rn.f32x2 %0,%1,%2,%3;" : "=l"(d) : "l"(a), "l"(b), "l"(c)); return d;
}
__device__ __forceinline__ ull pack2(float x, float y) {
    ull d; asm("mov.b64 %0,{%1,%2};" : "=l"(d) : "f"(x), "f"(y)); return d;
}
__device__ __forceinline__ float2 unpk2(ull a) {
    float2 r; asm("mov.b64 {%0,%1},%2;" : "=f"(r.x), "=f"(r.y) : "l"(a)); return r;
}

__device__ __forceinline__ uint32_t s2u(const void* p) {
    return (uint32_t)__cvta_generic_to_shared(p);
}
__device__ __forceinline__ uint32_t mapa_u32(uint32_t saddr, uint32_t rank) {
    uint32_t ra;
    asm("mapa.shared::cluster.u32 %0, %1, %2;" : "=r"(ra) : "r"(saddr), "r"(rank));
    return ra;
}
__device__ __forceinline__ void sts_cluster_b64(uint32_t ra, ull v) {
    asm volatile("st.shared::cluster.b64 [%0], %1;" :: "r"(ra), "l"(v) : "memory");
}
__device__ __forceinline__ void cluster_sync_() {
    asm volatile("barrier.cluster.arrive.aligned;\n\tbarrier.cluster.wait.aligned;" ::: "memory");
}
__device__ __forceinline__ uint32_t ctarank() {
    uint32_t r; asm("mov.u32 %0, %%cluster_ctarank;" : "=r"(r)); return r;
}

__device__ __forceinline__ float fsig(float x)  { return 1.0f / (1.0f + __expf(-x)); }
__device__ __forceinline__ float ftanh(float x) { return 2.0f / (1.0f + __expf(-2.0f * x)) - 1.0f; }

// ---------- scratch ----------
__device__ float g_xg[(size_t)MTOT * G4];
__device__ float g_y0[(size_t)MTOT * HH];
__device__ float g_y1[(size_t)MTOT * HH];

// ============================================================================
// Phase A: GEMM (unchanged)
// ============================================================================
__global__ void __launch_bounds__(256) gemm_kernel(
    const float* __restrict__ Ain, int useAin,
    const float* __restrict__ W,
    const float* __restrict__ b1, const float* __restrict__ b2)
{
    const float* A = useAin ? Ain : g_y0;
    float* C = g_xg;

    __shared__ float As[16][132];
    __shared__ float Bs[16][68];

    const int tid = threadIdx.x;
    const int bm = blockIdx.y * 128;
    const int bn = blockIdx.x * 64;
    const int tx = tid & 15;
    const int ty = tid >> 4;

    ull acc[8][2];
#pragma unroll
    for (int i = 0; i < 8; i++) { acc[i][0] = 0ull; acc[i][1] = 0ull; }

    for (int kt = 0; kt < HH; kt += 16) {
#pragma unroll
        for (int i = 0; i < 2; i++) {
            int idx = tid + i * 256;
            int r = idx >> 2, q = idx & 3;
            float4 v = *(const float4*)(A + (size_t)(bm + r) * HH + kt + q * 4);
            As[q * 4 + 0][r] = v.x; As[q * 4 + 1][r] = v.y;
            As[q * 4 + 2][r] = v.z; As[q * 4 + 3][r] = v.w;
        }
        {
            int r = tid >> 2, q = tid & 3;
            float4 v = *(const float4*)(W + (size_t)(bn + r) * HH + kt + q * 4);
            Bs[q * 4 + 0][r] = v.x; Bs[q * 4 + 1][r] = v.y;
            Bs[q * 4 + 2][r] = v.z; Bs[q * 4 + 3][r] = v.w;
        }
        __syncthreads();
#pragma unroll
        for (int k = 0; k < 16; k++) {
            float4 b4 = *(const float4*)&Bs[k][tx * 4];
            ull b01 = pack2(b4.x, b4.y);
            ull b23 = pack2(b4.z, b4.w);
            float4 a0 = *(const float4*)&As[k][ty * 8];
            float4 a1 = *(const float4*)&As[k][ty * 8 + 4];
            float am[8] = {a0.x, a0.y, a0.z, a0.w, a1.x, a1.y, a1.z, a1.w};
#pragma unroll
            for (int mi = 0; mi < 8; mi++) {
                ull ad = pack2(am[mi], am[mi]);
                acc[mi][0] = fma2(ad, b01, acc[mi][0]);
                acc[mi][1] = fma2(ad, b23, acc[mi][1]);
            }
        }
        __syncthreads();
    }

    float4 bias;
    bias.x = b1[bn + tx * 4 + 0] + b2[bn + tx * 4 + 0];
    bias.y = b1[bn + tx * 4 + 1] + b2[bn + tx * 4 + 1];
    bias.z = b1[bn + tx * 4 + 2] + b2[bn + tx * 4 + 2];
    bias.w = b1[bn + tx * 4 + 3] + b2[bn + tx * 4 + 3];
#pragma unroll
    for (int mi = 0; mi < 8; mi++) {
        float2 u = unpk2(acc[mi][0]);
        float2 v = unpk2(acc[mi][1]);
        float4 o = {u.x + bias.x, u.y + bias.y, v.x + bias.z, v.y + bias.w};
        *(float4*)(C + (size_t)(bm + ty * 8 + mi) * G4 + bn + tx * 4) = o;
    }
}

// ============================================================================
// Phase B v5: 8 clusters x 8 CTAs x 512 threads. Two batch groups per
// cluster (weights shared). 16 warps = 8 k-slices (32 k) x 2 row-halves:
// wp[32] = 64 regs/thread -> fits the 128-reg cap at 512 threads (R3 proved
// 124 regs with this geometry), giving 4 warps/SMSP to hide LDS latency.
// One __syncthreads + one cluster.sync per step covers both groups.
// ============================================================================
#define HD_GRP_BYTES (256 * 4 * 8)          // one [k][b] ull plane
#define HD_BUF_BYTES (2 * HD_GRP_BYTES)     // both groups of one buffer

struct RS {
    ull   hd[2][2][256][4];     // [buf][group][k][b], (h,h) duplicated  32KB
    float red[2][8][4][128];    // [group][kslice][b][row]               32KB
};

extern __shared__ __align__(16) char smem_raw[];

__global__ void __launch_bounds__(512, 1) __cluster_dims__(8, 1, 1)
rnn_kernel(const float* __restrict__ whh, int layer)
{
    RS* sm = (RS*)smem_raw;
    float* yout = layer ? g_y1 : g_y0;

    const int tid  = threadIdx.x;
    const int lane = tid & 31;
    const int wid  = tid >> 5;
    const int ks   = wid & 7;      // k-slice 0..7 (32 k each)
    const int rh   = wid >> 3;     // row half
    const int s    = (int)ctarank();
    const int cl   = blockIdx.x >> 3;
    const int b0   = cl * 8;       // 8 batches per cluster

    const int pr = rh * 32 + lane;       // row pair 0..63
    const int r0 = 2 * pr;
    const int grow0 = ((r0 >> 5) << 8) + s * 32 + (r0 & 31);
    const int kb = ks * 32;

    // ---- weights in registers: wp[k] = (w[r0][kb+k], w[r0+1][kb+k]) ----
    ull wp[32];
    {
        const float* w0p = whh + (size_t)grow0 * HH + kb;
        const float* w1p = w0p + HH;
#pragma unroll
        for (int q = 0; q < 8; q++) {
            float4 v0 = *(const float4*)(w0p + 4 * q);
            float4 v1 = *(const float4*)(w1p + 4 * q);
            wp[4 * q + 0] = pack2(v0.x, v1.x);
            wp[4 * q + 1] = pack2(v0.y, v1.y);
            wp[4 * q + 2] = pack2(v0.z, v1.z);
            wp[4 * q + 3] = pack2(v0.w, v1.w);
        }
    }

    // zero all h buffers (2 bufs x 2 groups)
    for (int i = tid; i < 2 * 2 * 256 * 4; i += 512) ((ull*)sm->hd)[i] = 0ull;
    __syncthreads();
    cluster_sync_();

    // ---- cell identity (threads 0..255 own one cell each) ----
    const int gsel = (tid >> 7) & 1;
    const int cb   = (tid >> 5) & 3;
    const int cd   = tid & 31;
    const int gb   = b0 + gsel * 4 + cb;                 // global batch
    const float* xgb = g_xg + (size_t)gb * TT * G4 + s * 32 + cd;
    float* youtp = yout + (size_t)gb * TT * HH + s * 32 + cd;
    const uint32_t la_buf0 = s2u(&sm->hd[0][gsel][s * 32 + cd][cb]);
    const bool is_cell = (tid < 256);

    float creg = 0.0f;

    for (int t = 0; t < TT; t++) {
        const int p = t & 1;

        // prefetch xg for this thread's cell (consumed after the k-loops)
        float xv0 = 0.f, xv1 = 0.f, xv2 = 0.f, xv3 = 0.f;
        if (is_cell) {
            const float* xp = xgb + (size_t)t * G4;
            xv0 = __ldg(xp);        xv1 = __ldg(xp + 256);
            xv2 = __ldg(xp + 512);  xv3 = __ldg(xp + 768);
        }

        // ---- k-loop, group A: 32 iters, 2x LDS.128 broadcast + 4x FFMA2 ----
        {
            ull a0 = 0ull, a1 = 0ull, a2 = 0ull, a3 = 0ull;
            const ulonglong2* hb = (const ulonglong2*)&sm->hd[p][0][kb][0];
#pragma unroll
            for (int kk = 0; kk < 32; kk++) {
                ulonglong2 h01 = hb[2 * kk];
                ulonglong2 h23 = hb[2 * kk + 1];
                ull w = wp[kk];
                a0 = fma2(w, h01.x, a0);
                a1 = fma2(w, h01.y, a1);
                a2 = fma2(w, h23.x, a2);
                a3 = fma2(w, h23.y, a3);
            }
            *(ull*)&sm->red[0][ks][0][r0] = a0;
            *(ull*)&sm->red[0][ks][1][r0] = a1;
            *(ull*)&sm->red[0][ks][2][r0] = a2;
            *(ull*)&sm->red[0][ks][3][r0] = a3;
        }
        // ---- k-loop, group B (same weights, independent h) ----
        {
            ull a0 = 0ull, a1 = 0ull, a2 = 0ull, a3 = 0ull;
            const ulonglong2* hb = (const ulonglong2*)&sm->hd[p][1][kb][0];
#pragma unroll
            for (int kk = 0; kk < 32; kk++) {
                ulonglong2 h01 = hb[2 * kk];
                ulonglong2 h23 = hb[2 * kk + 1];
                ull w = wp[kk];
                a0 = fma2(w, h01.x, a0);
                a1 = fma2(w, h01.y, a1);
                a2 = fma2(w, h23.x, a2);
                a3 = fma2(w, h23.y, a3);
            }
            *(ull*)&sm->red[1][ks][0][r0] = a0;
            *(ull*)&sm->red[1][ks][1][r0] = a1;
            *(ull*)&sm->red[1][ks][2][r0] = a2;
            *(ull*)&sm->red[1][ks][3][r0] = a3;
        }
        __syncthreads();

        // ---- merged reduce + activation + cell (threads 0..255) ----
        if (is_cell) {
            float si = xv0, sf = xv1, sg = xv2, so = xv3;
#pragma unroll
            for (int s8 = 0; s8 < 8; s8++) {
                si += sm->red[gsel][s8][cb][cd];
                sf += sm->red[gsel][s8][cb][32 + cd];
                sg += sm->red[gsel][s8][cb][64 + cd];
                so += sm->red[gsel][s8][cb][96 + cd];
            }
            float iv = fsig(si), fv = fsig(sf), gv = ftanh(sg), ov = fsig(so);
            creg = fv * creg + iv * gv;
            float hv = ov * ftanh(creg);
            youtp[(size_t)t * HH] = hv;

            // publish duplicated h to all 8 CTAs' buffer p^1
            ull hvd = pack2(hv, hv);
            const uint32_t la = la_buf0 + (uint32_t)((p ^ 1) * HD_BUF_BYTES);
#pragma unroll
            for (int rr = 0; rr < 8; rr++)
                sts_cluster_b64(mapa_u32(la, (uint32_t)rr), hvd);
        }
        cluster_sync_();
    }
}

// ============================================================================
// Head
// ============================================================================
__global__ void head_kernel(const float* __restrict__ wlin,
                            const float* __restrict__ blin,
                            float* __restrict__ out)
{
    int b = blockIdx.x, lane = threadIdx.x;
    const float* hp = g_y1 + ((size_t)b * TT + (TT - 1)) * HH;
    float ssum = 0.0f;
    for (int k = lane; k < HH; k += 32) ssum += hp[k] * wlin[k];
#pragma unroll
    for (int o = 16; o; o >>= 1) ssum += __shfl_down_sync(0xffffffffu, ssum, o);
    if (lane == 0) out[b] = ssum + blin[0];
}

// ============================================================================
extern "C" void kernel_launch(void* const* d_in, const int* in_sizes, int n_in,
                              void* d_out, int out_size)
{
    const float* input = (const float*)d_in[0];
    const float* w_ih  = (const float*)d_in[1];
    const float* w_hh  = (const float*)d_in[2];
    const float* b_ih  = (const float*)d_in[3];
    const float* b_hh  = (const float*)d_in[4];
    const float* w_lin = (const float*)d_in[5];
    const float* b_lin = (const float*)d_in[6];
    float* out = (float*)d_out;

    cudaFuncSetAttribute(rnn_kernel, cudaFuncAttributeMaxDynamicSharedMemorySize,
                         (int)sizeof(RS));

    dim3 gg(G4 / 64, MTOT / 128);

    gemm_kernel<<<gg, 256>>>(input, 1, w_ih, b_ih, b_hh);
    rnn_kernel<<<64, 512, sizeof(RS)>>>(w_hh, 0);
    gemm_kernel<<<gg, 256>>>(input, 0, w_ih + (size_t)G4 * HH, b_ih + G4, b_hh + G4);
    rnn_kernel<<<64, 512, sizeof(RS)>>>(w_hh + (size_t)G4 * HH, 1);
    head_kernel<<<BB, 32>>>(w_lin, b_lin, out);
}

// round 11
// speedup vs baseline: 2.2608x; 1.2274x over previous
#include <cuda_runtime.h>
#include <cstdint>

// Problem constants
#define BB 64
#define TT 2048
#define HH 256
#define G4 1024
#define MTOT (BB * TT)

typedef unsigned long long ull;

// ---------- f32x2 helpers ----------
__device__ __forceinline__ ull fma2(ull a, ull b, ull c) {
    ull d; asm("fma.rn.f32x2 %0,%1,%2,%3;" : "=l"(d) : "l"(a), "l"(b), "l"(c)); return d;
}
__device__ __forceinline__ ull pack2(float x, float y) {
    ull d; asm("mov.b64 %0,{%1,%2};" : "=l"(d) : "f"(x), "f"(y)); return d;
}
__device__ __forceinline__ float2 unpk2(ull a) {
    float2 r; asm("mov.b64 {%0,%1},%2;" : "=f"(r.x), "=f"(r.y) : "l"(a)); return r;
}
__device__ __forceinline__ float fold2(ull a) {
    float2 r = unpk2(a); return r.x + r.y;
}

__device__ __forceinline__ uint32_t s2u(const void* p) {
    return (uint32_t)__cvta_generic_to_shared(p);
}
__device__ __forceinline__ uint32_t mapa_u32(uint32_t saddr, uint32_t rank) {
    uint32_t ra;
    asm("mapa.shared::cluster.u32 %0, %1, %2;" : "=r"(ra) : "r"(saddr), "r"(rank));
    return ra;
}
__device__ __forceinline__ void sts_cluster_b32(uint32_t ra, float v) {
    asm volatile("st.shared::cluster.b32 [%0], %1;" :: "r"(ra), "f"(v) : "memory");
}
__device__ __forceinline__ void cluster_sync_() {
    asm volatile("barrier.cluster.arrive.aligned;\n\tbarrier.cluster.wait.aligned;" ::: "memory");
}
__device__ __forceinline__ uint32_t ctarank() {
    uint32_t r; asm("mov.u32 %0, %%cluster_ctarank;" : "=r"(r)); return r;
}

__device__ __forceinline__ float fsig(float x)  { return 1.0f / (1.0f + __expf(-x)); }
__device__ __forceinline__ float ftanh(float x) { return 2.0f / (1.0f + __expf(-2.0f * x)) - 1.0f; }

// ---------- scratch ----------
__device__ float g_xg[(size_t)MTOT * G4];
__device__ float g_y0[(size_t)MTOT * HH];
__device__ float g_y1[(size_t)MTOT * HH];

// ============================================================================
// Phase A: GEMM (unchanged)
// ============================================================================
__global__ void __launch_bounds__(256) gemm_kernel(
    const float* __restrict__ Ain, int useAin,
    const float* __restrict__ W,
    const float* __restrict__ b1, const float* __restrict__ b2)
{
    const float* A = useAin ? Ain : g_y0;
    float* C = g_xg;

    __shared__ float As[16][132];
    __shared__ float Bs[16][68];

    const int tid = threadIdx.x;
    const int bm = blockIdx.y * 128;
    const int bn = blockIdx.x * 64;
    const int tx = tid & 15;
    const int ty = tid >> 4;

    ull acc[8][2];
#pragma unroll
    for (int i = 0; i < 8; i++) { acc[i][0] = 0ull; acc[i][1] = 0ull; }

    for (int kt = 0; kt < HH; kt += 16) {
#pragma unroll
        for (int i = 0; i < 2; i++) {
            int idx = tid + i * 256;
            int r = idx >> 2, q = idx & 3;
            float4 v = *(const float4*)(A + (size_t)(bm + r) * HH + kt + q * 4);
            As[q * 4 + 0][r] = v.x; As[q * 4 + 1][r] = v.y;
            As[q * 4 + 2][r] = v.z; As[q * 4 + 3][r] = v.w;
        }
        {
            int r = tid >> 2, q = tid & 3;
            float4 v = *(const float4*)(W + (size_t)(bn + r) * HH + kt + q * 4);
            Bs[q * 4 + 0][r] = v.x; Bs[q * 4 + 1][r] = v.y;
            Bs[q * 4 + 2][r] = v.z; Bs[q * 4 + 3][r] = v.w;
        }
        __syncthreads();
#pragma unroll
        for (int k = 0; k < 16; k++) {
            float4 b4 = *(const float4*)&Bs[k][tx * 4];
            ull b01 = pack2(b4.x, b4.y);
            ull b23 = pack2(b4.z, b4.w);
            float4 a0 = *(const float4*)&As[k][ty * 8];
            float4 a1 = *(const float4*)&As[k][ty * 8 + 4];
            float am[8] = {a0.x, a0.y, a0.z, a0.w, a1.x, a1.y, a1.z, a1.w};
#pragma unroll
            for (int mi = 0; mi < 8; mi++) {
                ull ad = pack2(am[mi], am[mi]);
                acc[mi][0] = fma2(ad, b01, acc[mi][0]);
                acc[mi][1] = fma2(ad, b23, acc[mi][1]);
            }
        }
        __syncthreads();
    }

    float4 bias;
    bias.x = b1[bn + tx * 4 + 0] + b2[bn + tx * 4 + 0];
    bias.y = b1[bn + tx * 4 + 1] + b2[bn + tx * 4 + 1];
    bias.z = b1[bn + tx * 4 + 2] + b2[bn + tx * 4 + 2];
    bias.w = b1[bn + tx * 4 + 3] + b2[bn + tx * 4 + 3];
#pragma unroll
    for (int mi = 0; mi < 8; mi++) {
        float2 u = unpk2(acc[mi][0]);
        float2 v = unpk2(acc[mi][1]);
        float4 o = {u.x + bias.x, u.y + bias.y, v.x + bias.z, v.y + bias.w};
        *(float4*)(C + (size_t)(bm + ty * 8 + mi) * G4 + bn + tx * 4) = o;
    }
}

// ============================================================================
// Phase B v6: k-paired FFMA2.
// 8 clusters x 8 CTAs x 512 threads, 2 batch groups per cluster.
// h stored k-paired: hdk[buf][g][k2][b] = (h_{2k2}, h_{2k2+1}) for batch b.
// One FFMA2 = 2 MACs for one (row,batch); k-split folded at loop end.
// Per 2-k iter: 2x LDS.128 + 8x FFMA2 = 16 MACs (crossbar wavefronts halved
// vs R10). h published to peers as plain b32 floats (no duplication).
// ============================================================================
struct RS {
    ull   hdk[2][2][128][4];    // [buf][group][k2][b] = (h_2k2, h_2k2+1)  16KB
    float red[2][8][128][4];    // [group][kslice][row][b]                 32KB
};

#define HD_BUF_BYTES (2 * 128 * 4 * 8)      // one buffer (both groups) = 8KB

extern __shared__ __align__(16) char smem_raw[];

__global__ void __launch_bounds__(512, 1) __cluster_dims__(8, 1, 1)
rnn_kernel(const float* __restrict__ whh, int layer)
{
    RS* sm = (RS*)smem_raw;
    float* yout = layer ? g_y1 : g_y0;

    const int tid  = threadIdx.x;
    const int lane = tid & 31;
    const int wid  = tid >> 5;
    const int ks   = wid & 7;      // k-slice 0..7 (32 k = 16 k2 each)
    const int rh   = wid >> 3;     // row half
    const int s    = (int)ctarank();
    const int cl   = blockIdx.x >> 3;
    const int b0   = cl * 8;       // 8 batches per cluster

    const int pr = rh * 32 + lane;       // row pair 0..63
    const int r0 = 2 * pr;
    const int grow0 = ((r0 >> 5) << 8) + s * 32 + (r0 & 31);
    const int kb2 = ks * 16;             // k2 base

    // ---- weights in registers, k-paired per row:
    //   wp0[k2] = (w[r0][2k2], w[r0][2k2+1]),  wp1 same for r1 = r0+1
    ull wp0[16], wp1[16];
    {
        const float* w0p = whh + (size_t)grow0 * HH + kb2 * 2;
        const float* w1p = w0p + HH;
#pragma unroll
        for (int q = 0; q < 8; q++) {
            float4 v0 = *(const float4*)(w0p + 4 * q);
            float4 v1 = *(const float4*)(w1p + 4 * q);
            wp0[2 * q + 0] = pack2(v0.x, v0.y);
            wp0[2 * q + 1] = pack2(v0.z, v0.w);
            wp1[2 * q + 0] = pack2(v1.x, v1.y);
            wp1[2 * q + 1] = pack2(v1.z, v1.w);
        }
    }

    // zero all h buffers
    for (int i = tid; i < 2 * 2 * 128 * 4; i += 512) ((ull*)sm->hdk)[i] = 0ull;
    __syncthreads();
    cluster_sync_();

    // ---- cell identity (threads 0..255 own one cell each) ----
    const int gsel = (tid >> 7) & 1;
    const int cb   = (tid >> 5) & 3;
    const int cd   = tid & 31;
    const int gb   = b0 + gsel * 4 + cb;                 // global batch
    const int kd   = s * 32 + cd;                        // this cell's h dim
    const float* xgb = g_xg + (size_t)gb * TT * G4 + kd;
    float* youtp = yout + (size_t)gb * TT * HH + kd;
    // float slot of this cell's h in buf0 (lo/hi half of the k-pair)
    const uint32_t la_buf0 =
        s2u(&sm->hdk[0][gsel][kd >> 1][cb]) + (uint32_t)((kd & 1) * 4);
    const bool is_cell = (tid < 256);

    float creg = 0.0f;

    for (int t = 0; t < TT; t++) {
        const int p = t & 1;

        // prefetch xg for this thread's cell (consumed after the k-loops)
        float xv0 = 0.f, xv1 = 0.f, xv2 = 0.f, xv3 = 0.f;
        if (is_cell) {
            const float* xp = xgb + (size_t)t * G4;
            xv0 = __ldg(xp);        xv1 = __ldg(xp + 256);
            xv2 = __ldg(xp + 512);  xv3 = __ldg(xp + 768);
        }

        // ---- k-loops: 16 iters x (2 LDS.128 + 8 FFMA2) per group ----
#pragma unroll
        for (int g = 0; g < 2; g++) {
            ull a00 = 0ull, a01 = 0ull, a02 = 0ull, a03 = 0ull;
            ull a10 = 0ull, a11 = 0ull, a12 = 0ull, a13 = 0ull;
            const ulonglong2* hb = (const ulonglong2*)&sm->hdk[p][g][kb2][0];
#pragma unroll
            for (int kk = 0; kk < 16; kk++) {
                ulonglong2 hx = hb[2 * kk];       // b0:(h2k,h2k+1), b1:(...)
                ulonglong2 hy = hb[2 * kk + 1];   // b2, b3
                ull w0 = wp0[kk], w1 = wp1[kk];
                a00 = fma2(w0, hx.x, a00);
                a01 = fma2(w0, hx.y, a01);
                a02 = fma2(w0, hy.x, a02);
                a03 = fma2(w0, hy.y, a03);
                a10 = fma2(w1, hx.x, a10);
                a11 = fma2(w1, hx.y, a11);
                a12 = fma2(w1, hy.x, a12);
                a13 = fma2(w1, hy.y, a13);
            }
            // fold k-split halves, store per-row float4 partials
            float4 s0 = {fold2(a00), fold2(a01), fold2(a02), fold2(a03)};
            float4 s1 = {fold2(a10), fold2(a11), fold2(a12), fold2(a13)};
            *(float4*)&sm->red[g][ks][r0][0]     = s0;
            *(float4*)&sm->red[g][ks][r0 + 1][0] = s1;
        }
        __syncthreads();

        // ---- merged reduce + activation + cell (threads 0..255) ----
        if (is_cell) {
            float si = xv0, sf = xv1, sg = xv2, so = xv3;
#pragma unroll
            for (int s8 = 0; s8 < 8; s8++) {
                si += sm->red[gsel][s8][cd][cb];
                sf += sm->red[gsel][s8][32 + cd][cb];
                sg += sm->red[gsel][s8][64 + cd][cb];
                so += sm->red[gsel][s8][96 + cd][cb];
            }
            float iv = fsig(si), fv = fsig(sf), gv = ftanh(sg), ov = fsig(so);
            creg = fv * creg + iv * gv;
            float hv = ov * ftanh(creg);
            youtp[(size_t)t * HH] = hv;

            // publish plain h to all 8 CTAs' buffer p^1
            const uint32_t la = la_buf0 + (uint32_t)((p ^ 1) * HD_BUF_BYTES);
#pragma unroll
            for (int rr = 0; rr < 8; rr++)
                sts_cluster_b32(mapa_u32(la, (uint32_t)rr), hv);
        }
        cluster_sync_();
    }
}

// ============================================================================
// Head
// ============================================================================
__global__ void head_kernel(const float* __restrict__ wlin,
                            const float* __restrict__ blin,
                            float* __restrict__ out)
{
    int b = blockIdx.x, lane = threadIdx.x;
    const float* hp = g_y1 + ((size_t)b * TT + (TT - 1)) * HH;
    float ssum = 0.0f;
    for (int k = lane; k < HH; k += 32) ssum += hp[k] * wlin[k];
#pragma unroll
    for (int o = 16; o; o >>= 1) ssum += __shfl_down_sync(0xffffffffu, ssum, o);
    if (lane == 0) out[b] = ssum + blin[0];
}

// ============================================================================
extern "C" void kernel_launch(void* const* d_in, const int* in_sizes, int n_in,
                              void* d_out, int out_size)
{
    const float* input = (const float*)d_in[0];
    const float* w_ih  = (const float*)d_in[1];
    const float* w_hh  = (const float*)d_in[2];
    const float* b_ih  = (const float*)d_in[3];
    const float* b_hh  = (const float*)d_in[4];
    const float* w_lin = (const float*)d_in[5];
    const float* b_lin = (const float*)d_in[6];
    float* out = (float*)d_out;

    cudaFuncSetAttribute(rnn_kernel, cudaFuncAttributeMaxDynamicSharedMemorySize,
                         (int)sizeof(RS));

    dim3 gg(G4 / 64, MTOT / 128);

    gemm_kernel<<<gg, 256>>>(input, 1, w_ih, b_ih, b_hh);
    rnn_kernel<<<64, 512, sizeof(RS)>>>(w_hh, 0);
    gemm_kernel<<<gg, 256>>>(input, 0, w_ih + (size_t)G4 * HH, b_ih + G4, b_hh + G4);
    rnn_kernel<<<64, 512, sizeof(RS)>>>(w_hh + (size_t)G4 * HH, 1);
    head_kernel<<<BB, 32>>>(w_lin, b_lin, out);
}

// round 13
// speedup vs baseline: 2.5366x; 1.1220x over previous
#include <cuda_runtime.h>
#include <cstdint>

// Problem constants
#define BB 64
#define TT 2048
#define HH 256
#define G4 1024
#define MTOT (BB * TT)

typedef unsigned long long ull;

// ---------- f32x2 helpers ----------
__device__ __forceinline__ ull fma2(ull a, ull b, ull c) {
    ull d; asm("fma.rn.f32x2 %0,%1,%2,%3;" : "=l"(d) : "l"(a), "l"(b), "l"(c)); return d;
}
__device__ __forceinline__ ull pack2(float x, float y) {
    ull d; asm("mov.b64 %0,{%1,%2};" : "=l"(d) : "f"(x), "f"(y)); return d;
}
__device__ __forceinline__ float2 unpk2(ull a) {
    float2 r; asm("mov.b64 {%0,%1},%2;" : "=f"(r.x), "=f"(r.y) : "l"(a)); return r;
}
__device__ __forceinline__ float fold2(ull a) {
    float2 r = unpk2(a); return r.x + r.y;
}

__device__ __forceinline__ uint32_t s2u(const void* p) {
    return (uint32_t)__cvta_generic_to_shared(p);
}
__device__ __forceinline__ uint32_t mapa_u32(uint32_t saddr, uint32_t rank) {
    uint32_t ra;
    asm("mapa.shared::cluster.u32 %0, %1, %2;" : "=r"(ra) : "r"(saddr), "r"(rank));
    return ra;
}
__device__ __forceinline__ void sts_cluster_b32(uint32_t ra, float v) {
    asm volatile("st.shared::cluster.b32 [%0], %1;" :: "r"(ra), "f"(v) : "memory");
}
__device__ __forceinline__ void cluster_arrive_() {
    asm volatile("barrier.cluster.arrive.aligned;" ::: "memory");
}
__device__ __forceinline__ void cluster_wait_() {
    asm volatile("barrier.cluster.wait.aligned;" ::: "memory");
}
__device__ __forceinline__ void cluster_sync_() {
    asm volatile("barrier.cluster.arrive.aligned;\n\tbarrier.cluster.wait.aligned;" ::: "memory");
}
__device__ __forceinline__ uint32_t ctarank() {
    uint32_t r; asm("mov.u32 %0, %%cluster_ctarank;" : "=r"(r)); return r;
}

__device__ __forceinline__ float fsig(float x)  { return 1.0f / (1.0f + __expf(-x)); }
__device__ __forceinline__ float ftanh(float x) { return 2.0f / (1.0f + __expf(-2.0f * x)) - 1.0f; }

// ---------- scratch ----------
__device__ float g_xg[(size_t)MTOT * G4];
__device__ float g_y0[(size_t)MTOT * HH];
__device__ float g_y1[(size_t)MTOT * HH];

// ============================================================================
// Phase A: GEMM (unchanged)
// ============================================================================
__global__ void __launch_bounds__(256) gemm_kernel(
    const float* __restrict__ Ain, int useAin,
    const float* __restrict__ W,
    const float* __restrict__ b1, const float* __restrict__ b2)
{
    const float* A = useAin ? Ain : g_y0;
    float* C = g_xg;

    __shared__ float As[16][132];
    __shared__ float Bs[16][68];

    const int tid = threadIdx.x;
    const int bm = blockIdx.y * 128;
    const int bn = blockIdx.x * 64;
    const int tx = tid & 15;
    const int ty = tid >> 4;

    ull acc[8][2];
#pragma unroll
    for (int i = 0; i < 8; i++) { acc[i][0] = 0ull; acc[i][1] = 0ull; }

    for (int kt = 0; kt < HH; kt += 16) {
#pragma unroll
        for (int i = 0; i < 2; i++) {
            int idx = tid + i * 256;
            int r = idx >> 2, q = idx & 3;
            float4 v = *(const float4*)(A + (size_t)(bm + r) * HH + kt + q * 4);
            As[q * 4 + 0][r] = v.x; As[q * 4 + 1][r] = v.y;
            As[q * 4 + 2][r] = v.z; As[q * 4 + 3][r] = v.w;
        }
        {
            int r = tid >> 2, q = tid & 3;
            float4 v = *(const float4*)(W + (size_t)(bn + r) * HH + kt + q * 4);
            Bs[q * 4 + 0][r] = v.x; Bs[q * 4 + 1][r] = v.y;
            Bs[q * 4 + 2][r] = v.z; Bs[q * 4 + 3][r] = v.w;
        }
        __syncthreads();
#pragma unroll
        for (int k = 0; k < 16; k++) {
            float4 b4 = *(const float4*)&Bs[k][tx * 4];
            ull b01 = pack2(b4.x, b4.y);
            ull b23 = pack2(b4.z, b4.w);
            float4 a0 = *(const float4*)&As[k][ty * 8];
            float4 a1 = *(const float4*)&As[k][ty * 8 + 4];
            float am[8] = {a0.x, a0.y, a0.z, a0.w, a1.x, a1.y, a1.z, a1.w};
#pragma unroll
            for (int mi = 0; mi < 8; mi++) {
                ull ad = pack2(am[mi], am[mi]);
                acc[mi][0] = fma2(ad, b01, acc[mi][0]);
                acc[mi][1] = fma2(ad, b23, acc[mi][1]);
            }
        }
        __syncthreads();
    }

    float4 bias;
    bias.x = b1[bn + tx * 4 + 0] + b2[bn + tx * 4 + 0];
    bias.y = b1[bn + tx * 4 + 1] + b2[bn + tx * 4 + 1];
    bias.z = b1[bn + tx * 4 + 2] + b2[bn + tx * 4 + 2];
    bias.w = b1[bn + tx * 4 + 3] + b2[bn + tx * 4 + 3];
#pragma unroll
    for (int mi = 0; mi < 8; mi++) {
        float2 u = unpk2(acc[mi][0]);
        float2 v = unpk2(acc[mi][1]);
        float4 o = {u.x + bias.x, u.y + bias.y, v.x + bias.z, v.y + bias.w};
        *(float4*)(C + (size_t)(bm + ty * 8 + mi) * G4 + bn + tx * 4) = o;
    }
}

// ============================================================================
// Phase B v8: v6 core (k-paired FFMA2) + red in b-major layout
// [group][kslice][b][row]: reduce reads stride-1 conflict-free, stores are
// aligned b64 (row pair packed per batch, r0 even). Split cluster
// arrive/wait overlaps xg prefetch + peer skew with the barrier.
// ============================================================================
struct RS {
    ull   hdk[2][2][128][4];    // [buf][group][k2][b] = (h_2k2, h_2k2+1)  16KB
    float red[2][8][4][128];    // [group][kslice][b][row]                 32KB
};

#define HD_BUF_BYTES (2 * 128 * 4 * 8)      // one buffer (both groups) = 8KB

extern __shared__ __align__(16) char smem_raw[];

__global__ void __launch_bounds__(512, 1) __cluster_dims__(8, 1, 1)
rnn_kernel(const float* __restrict__ whh, int layer)
{
    RS* sm = (RS*)smem_raw;
    float* yout = layer ? g_y1 : g_y0;

    const int tid  = threadIdx.x;
    const int lane = tid & 31;
    const int wid  = tid >> 5;
    const int ks   = wid & 7;      // k-slice 0..7 (32 k = 16 k2 each)
    const int rh   = wid >> 3;     // row half
    const int s    = (int)ctarank();
    const int cl   = blockIdx.x >> 3;
    const int b0   = cl * 8;       // 8 batches per cluster

    const int pr = rh * 32 + lane;       // row pair 0..63
    const int r0 = 2 * pr;               // even -> b64 stores aligned
    const int grow0 = ((r0 >> 5) << 8) + s * 32 + (r0 & 31);
    const int kb2 = ks * 16;             // k2 base

    // ---- weights in registers, k-paired per row ----
    ull wp0[16], wp1[16];
    {
        const float* w0p = whh + (size_t)grow0 * HH + kb2 * 2;
        const float* w1p = w0p + HH;
#pragma unroll
        for (int q = 0; q < 8; q++) {
            float4 v0 = *(const float4*)(w0p + 4 * q);
            float4 v1 = *(const float4*)(w1p + 4 * q);
            wp0[2 * q + 0] = pack2(v0.x, v0.y);
            wp0[2 * q + 1] = pack2(v0.z, v0.w);
            wp1[2 * q + 0] = pack2(v1.x, v1.y);
            wp1[2 * q + 1] = pack2(v1.z, v1.w);
        }
    }

    // zero all h buffers
    for (int i = tid; i < 2 * 2 * 128 * 4; i += 512) ((ull*)sm->hdk)[i] = 0ull;
    __syncthreads();
    cluster_sync_();

    // ---- cell identity (threads 0..255 own one cell each) ----
    const int gsel = (tid >> 7) & 1;
    const int cb   = (tid >> 5) & 3;
    const int cd   = tid & 31;
    const int gb   = b0 + gsel * 4 + cb;                 // global batch
    const int kd   = s * 32 + cd;                        // this cell's h dim
    const float* xgb = g_xg + (size_t)gb * TT * G4 + kd;
    float* youtp = yout + (size_t)gb * TT * HH + kd;
    const uint32_t la_buf0 =
        s2u(&sm->hdk[0][gsel][kd >> 1][cb]) + (uint32_t)((kd & 1) * 4);
    const bool is_cell = (tid < 256);

    float creg = 0.0f;

    for (int t = 0; t < TT; t++) {
        const int p = t & 1;

        // prefetch xg BEFORE the barrier wait (overlaps load latency + skew)
        float xv0 = 0.f, xv1 = 0.f, xv2 = 0.f, xv3 = 0.f;
        if (is_cell) {
            const float* xp = xgb + (size_t)t * G4;
            xv0 = __ldg(xp);        xv1 = __ldg(xp + 256);
            xv2 = __ldg(xp + 512);  xv3 = __ldg(xp + 768);
        }
        if (t > 0) cluster_wait_();   // peers' h(t-1) publish now visible

        // ---- k-loops: 16 iters x (2 LDS.128 + 8 FFMA2) per group ----
#pragma unroll
        for (int g = 0; g < 2; g++) {
            ull a00 = 0ull, a01 = 0ull, a02 = 0ull, a03 = 0ull;
            ull a10 = 0ull, a11 = 0ull, a12 = 0ull, a13 = 0ull;
            const ulonglong2* hb = (const ulonglong2*)&sm->hdk[p][g][kb2][0];
#pragma unroll
            for (int kk = 0; kk < 16; kk++) {
                ulonglong2 hx = hb[2 * kk];       // b0:(h2k,h2k+1), b1
                ulonglong2 hy = hb[2 * kk + 1];   // b2, b3
                ull w0 = wp0[kk], w1 = wp1[kk];
                a00 = fma2(w0, hx.x, a00);
                a01 = fma2(w0, hx.y, a01);
                a02 = fma2(w0, hy.x, a02);
                a03 = fma2(w0, hy.y, a03);
                a10 = fma2(w1, hx.x, a10);
                a11 = fma2(w1, hx.y, a11);
                a12 = fma2(w1, hy.x, a12);
                a13 = fma2(w1, hy.y, a13);
            }
            // fold k-pairs; store (row r0, row r1) per batch as aligned b64
            *(ull*)&sm->red[g][ks][0][r0] = pack2(fold2(a00), fold2(a10));
            *(ull*)&sm->red[g][ks][1][r0] = pack2(fold2(a01), fold2(a11));
            *(ull*)&sm->red[g][ks][2][r0] = pack2(fold2(a02), fold2(a12));
            *(ull*)&sm->red[g][ks][3][r0] = pack2(fold2(a03), fold2(a13));
        }
        __syncthreads();

        // ---- merged reduce + activation + cell (threads 0..255) ----
        if (is_cell) {
            float si = xv0, sf = xv1, sg = xv2, so = xv3;
#pragma unroll
            for (int s8 = 0; s8 < 8; s8++) {   // stride-1 reads: conflict-free
                si += sm->red[gsel][s8][cb][cd];
                sf += sm->red[gsel][s8][cb][32 + cd];
                sg += sm->red[gsel][s8][cb][64 + cd];
                so += sm->red[gsel][s8][cb][96 + cd];
            }
            float iv = fsig(si), fv = fsig(sf), gv = ftanh(sg), ov = fsig(so);
            creg = fv * creg + iv * gv;
            float hv = ov * ftanh(creg);
            youtp[(size_t)t * HH] = hv;

            // publish plain h to all 8 CTAs' buffer p^1
            const uint32_t la = la_buf0 + (uint32_t)((p ^ 1) * HD_BUF_BYTES);
#pragma unroll
            for (int rr = 0; rr < 8; rr++)
                sts_cluster_b32(mapa_u32(la, (uint32_t)rr), hv);
        }
        cluster_arrive_();   // matched by wait at top of next step
    }
    cluster_wait_();   // consume final arrive; peers' last stores done
}

// ============================================================================
// Head
// ============================================================================
__global__ void head_kernel(const float* __restrict__ wlin,
                            const float* __restrict__ blin,
                            float* __restrict__ out)
{
    int b = blockIdx.x, lane = threadIdx.x;
    const float* hp = g_y1 + ((size_t)b * TT + (TT - 1)) * HH;
    float ssum = 0.0f;
    for (int k = lane; k < HH; k += 32) ssum += hp[k] * wlin[k];
#pragma unroll
    for (int o = 16; o; o >>= 1) ssum += __shfl_down_sync(0xffffffffu, ssum, o);
    if (lane == 0) out[b] = ssum + blin[0];
}

// ============================================================================
extern "C" void kernel_launch(void* const* d_in, const int* in_sizes, int n_in,
                              void* d_out, int out_size)
{
    const float* input = (const float*)d_in[0];
    const float* w_ih  = (const float*)d_in[1];
    const float* w_hh  = (const float*)d_in[2];
    const float* b_ih  = (const float*)d_in[3];
    const float* b_hh  = (const float*)d_in[4];
    const float* w_lin = (const float*)d_in[5];
    const float* b_lin = (const float*)d_in[6];
    float* out = (float*)d_out;

    cudaFuncSetAttribute(rnn_kernel, cudaFuncAttributeMaxDynamicSharedMemorySize,
                         (int)sizeof(RS));

    dim3 gg(G4 / 64, MTOT / 128);

    gemm_kernel<<<gg, 256>>>(input, 1, w_ih, b_ih, b_hh);
    rnn_kernel<<<64, 512, sizeof(RS)>>>(w_hh, 0);
    gemm_kernel<<<gg, 256>>>(input, 0, w_ih + (size_t)G4 * HH, b_ih + G4, b_hh + G4);
    rnn_kernel<<<64, 512, sizeof(RS)>>>(w_hh + (size_t)G4 * HH, 1);
    head_kernel<<<BB, 32>>>(w_lin, b_lin, out);
}